// round 1
// baseline (speedup 1.0000x reference)
#include <cuda_runtime.h>

// HyperConnections fused kernel for GB300 (sm_103a).
// b*l = NTOK tokens; per token: 4-stream LayerNorm stats + 5 dot products
// (folded into one 28-value block reduction via the identity
//  dot(norm_h, w) = rstd*(sum h*g*w - mu*sum g*w) + sum b*w),
// then out[n] = h_o*beta[n] + sum_m alpha[m][n]*h[m].
// h is read ONCE from HBM and held in registers for both phases.

constexpr int DIMC  = 2048;
constexpr int RATEC = 4;
constexpr int NW    = 5;          // 4 used alpha columns (k=1..4) + beta_fn
constexpr int TPB   = 256;
constexpr int VEC   = DIMC / TPB; // 8 floats per thread per stream
constexpr float DSCALE = 0.01f;
constexpr float EPSF   = 1e-5f;

// Token-independent precomputed data (scratch: __device__ globals, no allocs).
__device__ float g_W[NW][DIMC];   // g_W[j][d] = gamma[d] * w_j[d]
__device__ float g_S1[NW];        // sum_d gamma[d]*w_j[d]
__device__ float g_S2[NW];        // sum_d ln_beta[d]*w_j[d]

__global__ void precompute_k(const float* __restrict__ gamma,
                             const float* __restrict__ lbeta,
                             const float* __restrict__ afn,   // (DIM, 5)
                             const float* __restrict__ bfn) { // (DIM,)
    const int tid = threadIdx.x;
    float s1[NW], s2[NW];
#pragma unroll
    for (int j = 0; j < NW; j++) { s1[j] = 0.f; s2[j] = 0.f; }
    for (int d = tid; d < DIMC; d += TPB) {
        const float g = gamma[d], b = lbeta[d];
#pragma unroll
        for (int j = 0; j < NW; j++) {
            const float w = (j < 4) ? afn[d * 5 + j + 1] : bfn[d];
            g_W[j][d] = g * w;
            s1[j] += g * w;
            s2[j] += b * w;
        }
    }
#pragma unroll
    for (int j = 0; j < NW; j++) {
#pragma unroll
        for (int o = 16; o; o >>= 1) {
            s1[j] += __shfl_xor_sync(0xffffffffu, s1[j], o);
            s2[j] += __shfl_xor_sync(0xffffffffu, s2[j], o);
        }
    }
    __shared__ float sm[8][2 * NW];
    const int w = tid >> 5, lane = tid & 31;
    if (lane == 0) {
#pragma unroll
        for (int j = 0; j < NW; j++) { sm[w][j] = s1[j]; sm[w][NW + j] = s2[j]; }
    }
    __syncthreads();
    if (tid < 2 * NW) {
        float s = 0.f;
#pragma unroll
        for (int ww = 0; ww < 8; ww++) s += sm[ww][tid];
        if (tid < NW) g_S1[tid] = s;
        else          g_S2[tid - NW] = s;
    }
}

__global__ __launch_bounds__(TPB, 2) void hyper_k(
    const float* __restrict__ h,    // (NTOK, RATE, DIM)
    const float* __restrict__ h_o,  // (NTOK, DIM)
    const float* __restrict__ sA,   // static_alpha (RATE, 5)
    const float* __restrict__ sB,   // static_beta  (RATE,)
    float* __restrict__ out)        // (NTOK, RATE, DIM)
{
    const int t   = blockIdx.x;
    const int tid = threadIdx.x;
    const size_t hbase = (size_t)t * (RATEC * DIMC);
    const int d0 = tid * VEC;

    float hreg[RATEC][VEC];
    float p[RATEC][2 + NW];   // per-stream partials: sum_h, sum_h2, 5 dots

    // ---- Phase 1: load h (single HBM read), accumulate sums ----
#pragma unroll
    for (int n = 0; n < RATEC; n++) {
        const float4* src = (const float4*)(h + hbase + n * DIMC + d0);
        const float4 a = src[0], b = src[1];
        hreg[n][0]=a.x; hreg[n][1]=a.y; hreg[n][2]=a.z; hreg[n][3]=a.w;
        hreg[n][4]=b.x; hreg[n][5]=b.y; hreg[n][6]=b.z; hreg[n][7]=b.w;
        float sh = 0.f, sh2 = 0.f;
#pragma unroll
        for (int i = 0; i < VEC; i++) {
            sh  += hreg[n][i];
            sh2  = fmaf(hreg[n][i], hreg[n][i], sh2);
        }
        p[n][0] = sh; p[n][1] = sh2;
#pragma unroll
        for (int j = 0; j < NW; j++) p[n][2 + j] = 0.f;
    }

    // Dot products against the 5 fused weight columns (L2-resident, 40 KB).
#pragma unroll
    for (int j = 0; j < NW; j++) {
        const float4* wp = (const float4*)(&g_W[j][d0]);
        const float4 a = wp[0], b = wp[1];
        const float wv[VEC] = {a.x, a.y, a.z, a.w, b.x, b.y, b.z, b.w};
#pragma unroll
        for (int n = 0; n < RATEC; n++) {
            float s = p[n][2 + j];
#pragma unroll
            for (int i = 0; i < VEC; i++) s = fmaf(hreg[n][i], wv[i], s);
            p[n][2 + j] = s;
        }
    }

    // ---- Block reduction of 28 values ----
    float* pf = &p[0][0];
#pragma unroll
    for (int v = 0; v < RATEC * (2 + NW); v++) {
#pragma unroll
        for (int o = 16; o; o >>= 1)
            pf[v] += __shfl_xor_sync(0xffffffffu, pf[v], o);
    }
    __shared__ float sm[8][RATEC * (2 + NW)];
    __shared__ float fin[RATEC * (2 + NW)];
    const int w = tid >> 5, lane = tid & 31;
    if (lane == 0) {
#pragma unroll
        for (int v = 0; v < RATEC * (2 + NW); v++) sm[w][v] = pf[v];
    }
    __syncthreads();
    if (tid < RATEC * (2 + NW)) {
        float s = 0.f;
#pragma unroll
        for (int ww = 0; ww < 8; ww++) s += sm[ww][tid];
        fin[tid] = s;
    }
    __syncthreads();

    // ---- Every thread reconstructs alpha (4x4 used block) and beta ----
    float alpha[RATEC][RATEC];  // alpha[m][n] = alpha_full[m][n+1]
    float beta[RATEC];
    const float invD = 1.0f / DIMC;
#pragma unroll
    for (int m = 0; m < RATEC; m++) {
        const float mu   = fin[m * 7 + 0] * invD;
        const float var  = fin[m * 7 + 1] * invD - mu * mu;
        const float rstd = rsqrtf(var + EPSF);
#pragma unroll
        for (int j = 0; j < NW; j++) {
            const float dot = rstd * (fin[m * 7 + 2 + j] - mu * g_S1[j]) + g_S2[j];
            const float dyn = dot * DSCALE;
            if (j < 4) alpha[m][j] = dyn + sA[m * 5 + j + 1];
            else       beta[m]     = dyn + sB[m];
        }
    }

    // ---- Phase 2: mix + depth connection, h reused from registers ----
    const float4* hop = (const float4*)(h_o + (size_t)t * DIMC + d0);
    const float4 h0 = hop[0], h1 = hop[1];
    const float hov[VEC] = {h0.x, h0.y, h0.z, h0.w, h1.x, h1.y, h1.z, h1.w};
#pragma unroll
    for (int n = 0; n < RATEC; n++) {
        float ov[VEC];
#pragma unroll
        for (int i = 0; i < VEC; i++) {
            float acc = hov[i] * beta[n];
#pragma unroll
            for (int m = 0; m < RATEC; m++)
                acc = fmaf(alpha[m][n], hreg[m][i], acc);
            ov[i] = acc;
        }
        float4* dst = (float4*)(out + hbase + n * DIMC + d0);
        dst[0] = make_float4(ov[0], ov[1], ov[2], ov[3]);
        dst[1] = make_float4(ov[4], ov[5], ov[6], ov[7]);
    }
}

extern "C" void kernel_launch(void* const* d_in, const int* in_sizes, int n_in,
                              void* d_out, int out_size) {
    const float* h     = (const float*)d_in[0];
    const float* h_o   = (const float*)d_in[1];
    const float* gamma = (const float*)d_in[2];
    const float* lbeta = (const float*)d_in[3];
    const float* afn   = (const float*)d_in[4];
    const float* bfn   = (const float*)d_in[5];
    const float* sA    = (const float*)d_in[6];
    const float* sB    = (const float*)d_in[7];
    float* out = (float*)d_out;

    const int ntok = in_sizes[1] / DIMC;   // b*l from h_o element count

    precompute_k<<<1, TPB>>>(gamma, lbeta, afn, bfn);
    hyper_k<<<ntok, TPB>>>(h, h_o, sA, sB, out);
}